// round 1
// baseline (speedup 1.0000x reference)
#include <cuda_runtime.h>
#include <cuda_bf16.h>

// Problem constants (fixed by the dataset)
#define LL 32768   // sequence length
#define HH 256     // model dim
#define NS 512     // state dim (complex channels)
#define CT 128     // scan chunk length
#define NC 256     // number of chunks = LL/CT

// ---------------- device scratch (static globals; no runtime alloc) ----------
__device__ float2 g_bu[(size_t)LL * NS];   // Bu, then overwritten in-place with states
__device__ float2 g_chunk[NC * NS];        // per-chunk Horner sums
__device__ float2 g_pref[NC * NS];         // per-chunk carry-in prefix
__device__ float2 g_lam[NS];               // Lambda
__device__ float2 g_lamT[NS];              // Lambda^CT
__device__ float  g_gamma[NS];             // sqrt(1-|Lambda|^2)
__device__ float2 g_bn[NS * HH];           // gamma-scaled B (re, im)

__device__ __forceinline__ float2 cmul(float2 a, float2 b) {
    return make_float2(a.x * b.x - a.y * b.y, a.x * b.y + a.y * b.x);
}

// ---------------- setup: Lambda, gamma, Lambda^CT ---------------------------
__global__ void k_setup(const float* __restrict__ nu_log,
                        const float* __restrict__ theta_log) {
    int n = threadIdx.x;
    if (n >= NS) return;
    float nu    = expf(nu_log[n]);
    float theta = expf(theta_log[n]);
    float mag   = expf(-nu);                 // |Lambda|
    float2 lam  = make_float2(mag * cosf(theta), mag * sinf(theta));
    g_lam[n]   = lam;
    g_gamma[n] = sqrtf(fmaxf(1.0f - mag * mag, 0.0f));
    // Lambda^128 via 7 squarings
    float2 t = lam;
    #pragma unroll
    for (int i = 0; i < 7; i++) t = cmul(t, t);
    g_lamT[n] = t;
}

// ---------------- scale B by gamma ------------------------------------------
__global__ void k_bn(const float* __restrict__ Bre, const float* __restrict__ Bim) {
    int i = blockIdx.x * 256 + threadIdx.x;
    if (i >= NS * HH) return;
    int n = i / HH;
    float g = g_gamma[n];
    g_bn[i] = make_float2(Bre[i] * g, Bim[i] * g);
}

// ---------------- GEMM1: Bu[l,n] = sum_h U[l,h] * Bn[n,h] -------------------
// M = LL (rows l), N = NS (cols n), K = HH. 64x64 tile, BK=32, 256 threads,
// each thread computes a 4x4 micro-tile of (re, im) pairs.
__global__ __launch_bounds__(256) void k_gemm1(const float* __restrict__ U) {
    __shared__ float As[64][33];
    __shared__ float Br[64][33];
    __shared__ float Bi[64][33];

    int tx = threadIdx.x & 15;
    int ty = threadIdx.x >> 4;
    int row0 = blockIdx.x * 64;   // l base
    int col0 = blockIdx.y * 64;   // n base

    float accr[4][4] = {};
    float acci[4][4] = {};

    for (int k0 = 0; k0 < HH; k0 += 32) {
        #pragma unroll
        for (int i = 0; i < 8; i++) {
            int idx = threadIdx.x + i * 256;
            int r = idx >> 5, c = idx & 31;
            As[r][c] = U[(size_t)(row0 + r) * HH + k0 + c];
        }
        #pragma unroll
        for (int i = 0; i < 8; i++) {
            int idx = threadIdx.x + i * 256;
            int r = idx >> 5, c = idx & 31;
            float2 b = g_bn[(size_t)(col0 + r) * HH + k0 + c];
            Br[r][c] = b.x;
            Bi[r][c] = b.y;
        }
        __syncthreads();
        #pragma unroll
        for (int kk = 0; kk < 32; kk++) {
            float a[4], br[4], bi[4];
            #pragma unroll
            for (int i = 0; i < 4; i++) a[i] = As[ty * 4 + i][kk];
            #pragma unroll
            for (int j = 0; j < 4; j++) { br[j] = Br[tx * 4 + j][kk]; bi[j] = Bi[tx * 4 + j][kk]; }
            #pragma unroll
            for (int i = 0; i < 4; i++)
                #pragma unroll
                for (int j = 0; j < 4; j++) {
                    accr[i][j] = fmaf(a[i], br[j], accr[i][j]);
                    acci[i][j] = fmaf(a[i], bi[j], acci[i][j]);
                }
        }
        __syncthreads();
    }
    #pragma unroll
    for (int i = 0; i < 4; i++)
        #pragma unroll
        for (int j = 0; j < 4; j++) {
            int l = row0 + ty * 4 + i;
            int n = col0 + tx * 4 + j;
            g_bu[(size_t)l * NS + n] = make_float2(accr[i][j], acci[i][j]);
        }
}

// ---------------- chunk reduce: b_c[n] = Horner(Lambda, Bu chunk) -----------
// block = chunk c, thread = channel n
__global__ __launch_bounds__(512) void k_chunk() {
    int c = blockIdx.x;
    int n = threadIdx.x;
    float2 lam = g_lam[n];
    float2 b = make_float2(0.f, 0.f);
    size_t base = (size_t)c * CT * NS + n;
    #pragma unroll 4
    for (int j = 0; j < CT; j++) {
        float2 v = g_bu[base + (size_t)j * NS];
        float2 t = cmul(lam, b);
        b = make_float2(t.x + v.x, t.y + v.y);
    }
    g_chunk[c * NS + n] = b;
}

// ---------------- cross-chunk scan (1 block, 512 threads) -------------------
__global__ __launch_bounds__(512) void k_scan() {
    int n = threadIdx.x;
    float2 lamT = g_lamT[n];
    float2 p = make_float2(0.f, 0.f);
    for (int c = 0; c < NC; c++) {
        g_pref[c * NS + n] = p;                 // state before chunk c
        float2 b = g_chunk[c * NS + n];
        float2 t = cmul(lamT, p);
        p = make_float2(t.x + b.x, t.y + b.y);
    }
}

// ---------------- apply: states written in place into g_bu ------------------
__global__ __launch_bounds__(512) void k_apply() {
    int c = blockIdx.x;
    int n = threadIdx.x;
    float2 lam = g_lam[n];
    float2 carry = g_pref[c * NS + n];
    size_t base = (size_t)c * CT * NS + n;
    #pragma unroll 4
    for (int j = 0; j < CT; j++) {
        size_t idx = base + (size_t)j * NS;
        float2 v = g_bu[idx];
        float2 t = cmul(lam, carry);
        carry = make_float2(t.x + v.x, t.y + v.y);
        g_bu[idx] = carry;
    }
}

// ---------------- GEMM2: y[l,h] = sum_n (sr*Cre - si*Cim) + D[h]*U[l,h] -----
// M = LL, N = HH, K = NS. 64x64 tile, BK=32.
__global__ __launch_bounds__(256) void k_gemm2(const float* __restrict__ U,
                                               const float* __restrict__ Cre,
                                               const float* __restrict__ Cim,
                                               const float* __restrict__ D,
                                               float* __restrict__ Y) {
    __shared__ float Ar[64][33];
    __shared__ float Ai[64][33];
    __shared__ float Br[64][33];
    __shared__ float Bi[64][33];

    int tx = threadIdx.x & 15;
    int ty = threadIdx.x >> 4;
    int row0 = blockIdx.x * 64;   // l base
    int col0 = blockIdx.y * 64;   // h base

    float acc[4][4] = {};

    for (int k0 = 0; k0 < NS; k0 += 32) {
        #pragma unroll
        for (int i = 0; i < 8; i++) {
            int idx = threadIdx.x + i * 256;
            int r = idx >> 5, ccol = idx & 31;
            float2 s = g_bu[(size_t)(row0 + r) * NS + k0 + ccol];
            Ar[r][ccol] = s.x;
            Ai[r][ccol] = s.y;
        }
        #pragma unroll
        for (int i = 0; i < 8; i++) {
            int idx = threadIdx.x + i * 256;
            int r = idx >> 5, ccol = idx & 31;
            Br[r][ccol] = Cre[(size_t)(col0 + r) * NS + k0 + ccol];
            Bi[r][ccol] = Cim[(size_t)(col0 + r) * NS + k0 + ccol];
        }
        __syncthreads();
        #pragma unroll
        for (int kk = 0; kk < 32; kk++) {
            float ar[4], ai[4], br[4], bi[4];
            #pragma unroll
            for (int i = 0; i < 4; i++) { ar[i] = Ar[ty * 4 + i][kk]; ai[i] = Ai[ty * 4 + i][kk]; }
            #pragma unroll
            for (int j = 0; j < 4; j++) { br[j] = Br[tx * 4 + j][kk]; bi[j] = Bi[tx * 4 + j][kk]; }
            #pragma unroll
            for (int i = 0; i < 4; i++)
                #pragma unroll
                for (int j = 0; j < 4; j++) {
                    acc[i][j] = fmaf(ar[i], br[j], acc[i][j]);
                    acc[i][j] = fmaf(-ai[i], bi[j], acc[i][j]);
                }
        }
        __syncthreads();
    }
    #pragma unroll
    for (int i = 0; i < 4; i++) {
        int l = row0 + ty * 4 + i;
        #pragma unroll
        for (int j = 0; j < 4; j++) {
            int h = col0 + tx * 4 + j;
            float d = D[h];
            float u = U[(size_t)l * HH + h];
            Y[(size_t)l * HH + h] = acc[i][j] + d * u;
        }
    }
}

// ---------------- launch ----------------------------------------------------
extern "C" void kernel_launch(void* const* d_in, const int* in_sizes, int n_in,
                              void* d_out, int out_size) {
    const float* U        = (const float*)d_in[0];
    const float* nu_log   = (const float*)d_in[1];
    const float* theta_lg = (const float*)d_in[2];
    const float* Bre      = (const float*)d_in[3];
    const float* Bim      = (const float*)d_in[4];
    const float* Cre      = (const float*)d_in[5];
    const float* Cim      = (const float*)d_in[6];
    const float* D        = (const float*)d_in[7];
    float* Y = (float*)d_out;

    k_setup<<<1, 512>>>(nu_log, theta_lg);
    k_bn<<<(NS * HH + 255) / 256, 256>>>(Bre, Bim);
    k_gemm1<<<dim3(LL / 64, NS / 64), 256>>>(U);
    k_chunk<<<NC, 512>>>();
    k_scan<<<1, 512>>>();
    k_apply<<<NC, 512>>>();
    k_gemm2<<<dim3(LL / 64, HH / 64), 256>>>(U, Cre, Cim, D, Y);
}

// round 2
// speedup vs baseline: 1.5013x; 1.5013x over previous
#include <cuda_runtime.h>
#include <cuda_bf16.h>
#include <cstdint>

#define LL 32768   // sequence length
#define HH 256     // model dim
#define NS 512     // state dim (complex channels)
#define CT 128     // scan chunk length
#define NC 256     // number of chunks = LL/CT

// ---------------- device scratch (static globals; no runtime alloc) ----------
__device__ float  g_re[(size_t)LL * NS];    // Bu real -> states real (in place)
__device__ float  g_im[(size_t)LL * NS];    // Bu imag -> states imag (in place)
__device__ float2 g_chunk[NC * NS];
__device__ float2 g_pref[NC * NS];
__device__ float2 g_lam[NS];
__device__ float2 g_lamT[NS];
__device__ float  g_gamma[NS];
__device__ float  g_bcat[2 * NS * HH];      // [1024][256]: rows 0..511 = Bre*gamma, 512.. = Bim*gamma
__device__ float  g_cc[HH * 2 * NS];        // [256][1024]: cols 0..511 = Cre, 512.. = -Cim

__device__ __forceinline__ float2 cmul(float2 a, float2 b) {
    return make_float2(a.x * b.x - a.y * b.y, a.x * b.y + a.y * b.x);
}

// ---------------- small helpers ---------------------------------------------
__device__ __forceinline__ void cpa16(void* dst_smem, const void* src) {
    uint32_t d = (uint32_t)__cvta_generic_to_shared(dst_smem);
    asm volatile("cp.async.cg.shared.global [%0], [%1], 16;" :: "r"(d), "l"(src));
}
#define CPA_COMMIT asm volatile("cp.async.commit_group;")

__device__ __forceinline__ void split_tf32(float x, uint32_t& hi, uint32_t& lo) {
    uint32_t h;
    asm("cvt.rna.tf32.f32 %0, %1;" : "=r"(h) : "f"(x));
    float hf = __uint_as_float(h);
    float l = x - hf;
    asm("cvt.rna.tf32.f32 %0, %1;" : "=r"(lo) : "f"(l));
    hi = h;
}

__device__ __forceinline__ void mma8(float* c, const uint32_t* a, const uint32_t* b) {
    asm volatile(
        "mma.sync.aligned.m16n8k8.row.col.f32.tf32.tf32.f32 "
        "{%0,%1,%2,%3},{%4,%5,%6,%7},{%8,%9},{%0,%1,%2,%3};"
        : "+f"(c[0]), "+f"(c[1]), "+f"(c[2]), "+f"(c[3])
        : "r"(a[0]), "r"(a[1]), "r"(a[2]), "r"(a[3]), "r"(b[0]), "r"(b[1]));
}

// ---------------- setup -----------------------------------------------------
__global__ void k_setup(const float* __restrict__ nu_log,
                        const float* __restrict__ theta_log) {
    int n = threadIdx.x;
    if (n >= NS) return;
    float nu    = expf(nu_log[n]);
    float theta = expf(theta_log[n]);
    float mag   = expf(-nu);
    float2 lam  = make_float2(mag * cosf(theta), mag * sinf(theta));
    g_lam[n]   = lam;
    g_gamma[n] = sqrtf(fmaxf(1.0f - mag * mag, 0.0f));
    float2 t = lam;
    #pragma unroll
    for (int i = 0; i < 7; i++) t = cmul(t, t);
    g_lamT[n] = t;
}

__global__ void k_bn(const float* __restrict__ Bre, const float* __restrict__ Bim) {
    int i = blockIdx.x * 256 + threadIdx.x;
    if (i >= NS * HH) return;
    int n = i / HH;
    int h = i % HH;
    float g = g_gamma[n];
    g_bcat[(size_t)n * HH + h]        = Bre[i] * g;
    g_bcat[(size_t)(n + NS) * HH + h] = Bim[i] * g;
}

__global__ void k_cc(const float* __restrict__ Cre, const float* __restrict__ Cim) {
    int i = blockIdx.x * 256 + threadIdx.x;
    if (i >= HH * NS) return;
    int h = i / NS;
    int n = i % NS;
    g_cc[(size_t)h * (2 * NS) + n]      = Cre[i];
    g_cc[(size_t)h * (2 * NS) + NS + n] = -Cim[i];
}

// ---------------- shared GEMM machinery --------------------------------------
// Block tile 128(M) x 64(N) x 16(K); 256 threads = 8 warps in 4(M) x 2(N);
// each warp owns a 32x32 tile = 2x4 mma(16x8) tiles; 3xTF32 split.

__device__ __forceinline__ void ld_tile(float (*As_)[20], float (*Bs_)[20],
                                        const float* Ag, int lda,
                                        const float* Bg, int ldb, int t) {
    #pragma unroll
    for (int i = 0; i < 2; i++) {
        int idx = t + i * 256;
        int r = idx >> 2, kc = idx & 3;
        cpa16(&As_[r][kc * 4], Ag + (size_t)r * lda + kc * 4);
    }
    {
        int r = t >> 2, kc = t & 3;
        cpa16(&Bs_[r][kc * 4], Bg + (size_t)r * ldb + kc * 4);
    }
}

__device__ __forceinline__ void mma_stage(const float (*A)[20], const float (*B)[20],
                                          float acc[2][4][4],
                                          int wm, int wn, int g, int t4) {
    #pragma unroll
    for (int ks = 0; ks < 16; ks += 8) {
        uint32_t ahi[2][4], alo[2][4];
        #pragma unroll
        for (int mi = 0; mi < 2; mi++) {
            int r0 = wm * 32 + mi * 16;
            float v0 = A[r0 + g][ks + t4];
            float v1 = A[r0 + g + 8][ks + t4];
            float v2 = A[r0 + g][ks + t4 + 4];
            float v3 = A[r0 + g + 8][ks + t4 + 4];
            split_tf32(v0, ahi[mi][0], alo[mi][0]);
            split_tf32(v1, ahi[mi][1], alo[mi][1]);
            split_tf32(v2, ahi[mi][2], alo[mi][2]);
            split_tf32(v3, ahi[mi][3], alo[mi][3]);
        }
        uint32_t bhi[4][2], blo[4][2];
        #pragma unroll
        for (int ni = 0; ni < 4; ni++) {
            int c0 = wn * 32 + ni * 8 + g;
            float v0 = B[c0][ks + t4];
            float v1 = B[c0][ks + t4 + 4];
            split_tf32(v0, bhi[ni][0], blo[ni][0]);
            split_tf32(v1, bhi[ni][1], blo[ni][1]);
        }
        #pragma unroll
        for (int mi = 0; mi < 2; mi++)
            #pragma unroll
            for (int ni = 0; ni < 4; ni++) {
                mma8(acc[mi][ni], alo[mi], bhi[ni]);
                mma8(acc[mi][ni], ahi[mi], blo[ni]);
                mma8(acc[mi][ni], ahi[mi], bhi[ni]);
            }
    }
}

// ---------------- GEMM1: Bu[L,1024] = U[L,256] @ g_bcat^T --------------------
// grid (16, 256): x = n'-tile (0..15, n'=x*64), y = m-tile
__global__ __launch_bounds__(256) void k_gemm1(const float* __restrict__ U) {
    __shared__ __align__(16) float As[2][128][20];
    __shared__ __align__(16) float Bs[2][64][20];
    int t = threadIdx.x;
    int w = t >> 5, lane = t & 31, g = lane >> 2, t4 = lane & 3;
    int wm = w >> 1, wn = w & 1;
    int row0 = blockIdx.y * 128;
    int col0 = blockIdx.x * 64;   // n' base in [0,1024)

    float acc[2][4][4] = {};
    const int KT = HH / 16;       // 16

    ld_tile(As[0], Bs[0], U + (size_t)row0 * HH, HH,
            g_bcat + (size_t)col0 * HH, HH, t);
    CPA_COMMIT;

    for (int it = 0; it < KT; it++) {
        if (it + 1 < KT) {
            int k0 = (it + 1) * 16;
            ld_tile(As[(it + 1) & 1], Bs[(it + 1) & 1],
                    U + (size_t)row0 * HH + k0, HH,
                    g_bcat + (size_t)col0 * HH + k0, HH, t);
            CPA_COMMIT;
            asm volatile("cp.async.wait_group 1;");
        } else {
            asm volatile("cp.async.wait_group 0;");
        }
        __syncthreads();
        mma_stage(As[it & 1], Bs[it & 1], acc, wm, wn, g, t4);
        __syncthreads();
    }

    float* out = (col0 >= NS) ? g_im : g_re;
    int nbase0 = (col0 & (NS - 1)) + wn * 32;
    #pragma unroll
    for (int mi = 0; mi < 2; mi++) {
        int l0 = row0 + wm * 32 + mi * 16 + g;
        #pragma unroll
        for (int ni = 0; ni < 4; ni++) {
            int nn = nbase0 + ni * 8 + 2 * t4;
            *(float2*)&out[(size_t)l0 * NS + nn] =
                make_float2(acc[mi][ni][0], acc[mi][ni][1]);
            *(float2*)&out[(size_t)(l0 + 8) * NS + nn] =
                make_float2(acc[mi][ni][2], acc[mi][ni][3]);
        }
    }
}

// ---------------- chunk reduce ----------------------------------------------
__global__ __launch_bounds__(512) void k_chunk() {
    int c = blockIdx.x;
    int n = threadIdx.x;
    float2 lam = g_lam[n];
    float2 b = make_float2(0.f, 0.f);
    size_t base = (size_t)c * CT * NS + n;
    #pragma unroll 4
    for (int j = 0; j < CT; j++) {
        size_t idx = base + (size_t)j * NS;
        float vr = g_re[idx], vi = g_im[idx];
        float2 tt = cmul(lam, b);
        b = make_float2(tt.x + vr, tt.y + vi);
    }
    g_chunk[c * NS + n] = b;
}

// ---------------- cross-chunk scan ------------------------------------------
__global__ __launch_bounds__(512) void k_scan() {
    int n = threadIdx.x;
    float2 lamT = g_lamT[n];
    float2 p = make_float2(0.f, 0.f);
    for (int c = 0; c < NC; c++) {
        g_pref[c * NS + n] = p;
        float2 b = g_chunk[c * NS + n];
        float2 tt = cmul(lamT, p);
        p = make_float2(tt.x + b.x, tt.y + b.y);
    }
}

// ---------------- apply: states in place ------------------------------------
__global__ __launch_bounds__(512) void k_apply() {
    int c = blockIdx.x;
    int n = threadIdx.x;
    float2 lam = g_lam[n];
    float2 carry = g_pref[c * NS + n];
    size_t base = (size_t)c * CT * NS + n;
    #pragma unroll 4
    for (int j = 0; j < CT; j++) {
        size_t idx = base + (size_t)j * NS;
        float vr = g_re[idx], vi = g_im[idx];
        float2 tt = cmul(lam, carry);
        carry = make_float2(tt.x + vr, tt.y + vi);
        g_re[idx] = carry.x;
        g_im[idx] = carry.y;
    }
}

// ---------------- GEMM2: Y[L,256] = S[L,1024] @ g_cc^T + D*U -----------------
// grid (4, 256): x = h-tile, y = m-tile. K = 1024 (k<512 -> g_re, else g_im)
__global__ __launch_bounds__(256) void k_gemm2(const float* __restrict__ U,
                                               const float* __restrict__ Dg,
                                               float* __restrict__ Y) {
    __shared__ __align__(16) float As[2][128][20];
    __shared__ __align__(16) float Bs[2][64][20];
    int t = threadIdx.x;
    int w = t >> 5, lane = t & 31, g = lane >> 2, t4 = lane & 3;
    int wm = w >> 1, wn = w & 1;
    int row0 = blockIdx.y * 128;
    int col0 = blockIdx.x * 64;   // h base

    float acc[2][4][4] = {};
    const int KT = (2 * NS) / 16; // 64

    {
        const float* Ap = g_re + (size_t)row0 * NS;   // k0 = 0
        ld_tile(As[0], Bs[0], Ap, NS, g_cc + (size_t)col0 * (2 * NS), 2 * NS, t);
        CPA_COMMIT;
    }

    for (int it = 0; it < KT; it++) {
        if (it + 1 < KT) {
            int k0 = (it + 1) * 16;
            const float* Ap = ((k0 < NS) ? g_re : g_im) + (size_t)row0 * NS + (k0 & (NS - 1));
            ld_tile(As[(it + 1) & 1], Bs[(it + 1) & 1], Ap, NS,
                    g_cc + (size_t)col0 * (2 * NS) + k0, 2 * NS, t);
            CPA_COMMIT;
            asm volatile("cp.async.wait_group 1;");
        } else {
            asm volatile("cp.async.wait_group 0;");
        }
        __syncthreads();
        mma_stage(As[it & 1], Bs[it & 1], acc, wm, wn, g, t4);
        __syncthreads();
    }

    #pragma unroll
    for (int mi = 0; mi < 2; mi++) {
        int l0 = row0 + wm * 32 + mi * 16 + g;
        #pragma unroll
        for (int ni = 0; ni < 4; ni++) {
            int h = col0 + wn * 32 + ni * 8 + 2 * t4;
            float2 d2 = *(const float2*)&Dg[h];
            float2 u0 = *(const float2*)&U[(size_t)l0 * HH + h];
            float2 u1 = *(const float2*)&U[(size_t)(l0 + 8) * HH + h];
            *(float2*)&Y[(size_t)l0 * HH + h] =
                make_float2(acc[mi][ni][0] + d2.x * u0.x, acc[mi][ni][1] + d2.y * u0.y);
            *(float2*)&Y[(size_t)(l0 + 8) * HH + h] =
                make_float2(acc[mi][ni][2] + d2.x * u1.x, acc[mi][ni][3] + d2.y * u1.y);
        }
    }
}

// ---------------- launch ----------------------------------------------------
extern "C" void kernel_launch(void* const* d_in, const int* in_sizes, int n_in,
                              void* d_out, int out_size) {
    const float* U        = (const float*)d_in[0];
    const float* nu_log   = (const float*)d_in[1];
    const float* theta_lg = (const float*)d_in[2];
    const float* Bre      = (const float*)d_in[3];
    const float* Bim      = (const float*)d_in[4];
    const float* Cre      = (const float*)d_in[5];
    const float* Cim      = (const float*)d_in[6];
    const float* D        = (const float*)d_in[7];
    float* Y = (float*)d_out;

    k_setup<<<1, 512>>>(nu_log, theta_lg);
    k_bn<<<(NS * HH + 255) / 256, 256>>>(Bre, Bim);
    k_cc<<<(HH * NS + 255) / 256, 256>>>(Cre, Cim);
    k_gemm1<<<dim3(16, 256), 256>>>(U);
    k_chunk<<<NC, 512>>>();
    k_scan<<<1, 512>>>();
    k_apply<<<NC, 512>>>();
    k_gemm2<<<dim3(4, 256), 256>>>(U, D, Y);
}

// round 3
// speedup vs baseline: 1.9158x; 1.2761x over previous
#include <cuda_runtime.h>
#include <cuda_bf16.h>
#include <cstdint>

#define LL 32768   // sequence length
#define HH 256     // model dim
#define NS 512     // state dim (complex channels)
#define CT 128     // scan chunk length
#define NC 256     // number of chunks = LL/CT
#define KP 24      // smem row stride in bf16 (16 + 8 pad -> conflict-free u32 loads)

// ---------------- device scratch (static globals; no runtime alloc) ----------
__device__ float  g_re[(size_t)LL * NS];           // Bu real (gemm1 out, scan in)
__device__ float  g_im[(size_t)LL * NS];           // Bu imag
__device__ __nv_bfloat16 g_shi[(size_t)LL * 2 * NS];  // states [L][1024] hi (re|im)
__device__ __nv_bfloat16 g_slo[(size_t)LL * 2 * NS];  // states lo
__device__ __nv_bfloat16 g_uhi[(size_t)LL * HH];
__device__ __nv_bfloat16 g_ulo[(size_t)LL * HH];
__device__ __nv_bfloat16 g_bchi[2 * NS * HH];      // [1024][256] gamma-scaled B hi
__device__ __nv_bfloat16 g_bclo[2 * NS * HH];
__device__ __nv_bfloat16 g_cchi[HH * 2 * NS];      // [256][1024]: Cre | -Cim, hi
__device__ __nv_bfloat16 g_cclo[HH * 2 * NS];
__device__ float2 g_chunk[NC * NS];
__device__ float2 g_pref[NC * NS];
__device__ float2 g_lam[NS];
__device__ float2 g_lamT[NS];
__device__ float  g_gamma[NS];

__device__ __forceinline__ float2 cmul(float2 a, float2 b) {
    return make_float2(a.x * b.x - a.y * b.y, a.x * b.y + a.y * b.x);
}

__device__ __forceinline__ void bf16_split(float x, __nv_bfloat16& hi, __nv_bfloat16& lo) {
    hi = __float2bfloat16_rn(x);
    lo = __float2bfloat16_rn(x - __bfloat162float(hi));
}

__device__ __forceinline__ void cpa16(void* dst_smem, const void* src) {
    uint32_t d = (uint32_t)__cvta_generic_to_shared(dst_smem);
    asm volatile("cp.async.cg.shared.global [%0], [%1], 16;" :: "r"(d), "l"(src));
}
#define CPA_COMMIT asm volatile("cp.async.commit_group;")

__device__ __forceinline__ void mma16(float* c, const uint32_t* a, const uint32_t* b) {
    asm volatile(
        "mma.sync.aligned.m16n8k16.row.col.f32.bf16.bf16.f32 "
        "{%0,%1,%2,%3},{%4,%5,%6,%7},{%8,%9},{%0,%1,%2,%3};"
        : "+f"(c[0]), "+f"(c[1]), "+f"(c[2]), "+f"(c[3])
        : "r"(a[0]), "r"(a[1]), "r"(a[2]), "r"(a[3]), "r"(b[0]), "r"(b[1]));
}

// ---------------- setup -----------------------------------------------------
__global__ void k_setup(const float* __restrict__ nu_log,
                        const float* __restrict__ theta_log) {
    int n = threadIdx.x;
    if (n >= NS) return;
    float nu    = expf(nu_log[n]);
    float theta = expf(theta_log[n]);
    float mag   = expf(-nu);
    float2 lam  = make_float2(mag * cosf(theta), mag * sinf(theta));
    g_lam[n]   = lam;
    g_gamma[n] = sqrtf(fmaxf(1.0f - mag * mag, 0.0f));
    float2 t = lam;
    #pragma unroll
    for (int i = 0; i < 7; i++) t = cmul(t, t);
    g_lamT[n] = t;
}

__global__ void k_splitU(const float* __restrict__ U) {
    size_t i = ((size_t)blockIdx.x * 256 + threadIdx.x) * 4;
    if (i >= (size_t)LL * HH) return;
    float4 v = *(const float4*)&U[i];
    __nv_bfloat16 h0, h1, h2, h3, l0, l1, l2, l3;
    bf16_split(v.x, h0, l0); bf16_split(v.y, h1, l1);
    bf16_split(v.z, h2, l2); bf16_split(v.w, h3, l3);
    *(__nv_bfloat162*)&g_uhi[i]     = __nv_bfloat162(h0, h1);
    *(__nv_bfloat162*)&g_uhi[i + 2] = __nv_bfloat162(h2, h3);
    *(__nv_bfloat162*)&g_ulo[i]     = __nv_bfloat162(l0, l1);
    *(__nv_bfloat162*)&g_ulo[i + 2] = __nv_bfloat162(l2, l3);
}

__global__ void k_bn(const float* __restrict__ Bre, const float* __restrict__ Bim) {
    int i = blockIdx.x * 256 + threadIdx.x;
    if (i >= NS * HH) return;
    int n = i / HH, h = i % HH;
    float g = g_gamma[n];
    __nv_bfloat16 hi, lo;
    bf16_split(Bre[i] * g, hi, lo);
    g_bchi[(size_t)n * HH + h] = hi;  g_bclo[(size_t)n * HH + h] = lo;
    bf16_split(Bim[i] * g, hi, lo);
    g_bchi[(size_t)(n + NS) * HH + h] = hi;  g_bclo[(size_t)(n + NS) * HH + h] = lo;
}

__global__ void k_cc(const float* __restrict__ Cre, const float* __restrict__ Cim) {
    int i = blockIdx.x * 256 + threadIdx.x;
    if (i >= HH * NS) return;
    int h = i / NS, n = i % NS;
    __nv_bfloat16 hi, lo;
    bf16_split(Cre[i], hi, lo);
    g_cchi[(size_t)h * (2 * NS) + n] = hi;  g_cclo[(size_t)h * (2 * NS) + n] = lo;
    bf16_split(-Cim[i], hi, lo);
    g_cchi[(size_t)h * (2 * NS) + NS + n] = hi;  g_cclo[(size_t)h * (2 * NS) + NS + n] = lo;
}

// ---------------- shared GEMM machinery --------------------------------------
// Block tile 128(M) x 64(N) x 16(K) bf16; 256 threads = 8 warps 4(M)x2(N);
// warp tile 32x32 = 2x4 m16n8k16 mmas, 3 passes (hihi + lohi + hilo).

__device__ __forceinline__ void ld_stage(
    __nv_bfloat16 (*Ahi)[KP], __nv_bfloat16 (*Alo)[KP],
    __nv_bfloat16 (*Bhi)[KP], __nv_bfloat16 (*Blo)[KP],
    const __nv_bfloat16* gAh, const __nv_bfloat16* gAl, int lda,
    const __nv_bfloat16* gBh, const __nv_bfloat16* gBl, int ldb, int t) {
    {
        int r = t >> 1, kc = t & 1;                       // 128 rows x 2 chunks
        cpa16(&Ahi[r][kc * 8], gAh + (size_t)r * lda + kc * 8);
        cpa16(&Alo[r][kc * 8], gAl + (size_t)r * lda + kc * 8);
    }
    if (t < 128) {
        int r = t >> 1, kc = t & 1;                       // 64 rows x 2 chunks
        cpa16(&Bhi[r][kc * 8], gBh + (size_t)r * ldb + kc * 8);
        cpa16(&Blo[r][kc * 8], gBl + (size_t)r * ldb + kc * 8);
    }
}

__device__ __forceinline__ void mma_stage(
    const __nv_bfloat16 (*Ahi)[KP], const __nv_bfloat16 (*Alo)[KP],
    const __nv_bfloat16 (*Bhi)[KP], const __nv_bfloat16 (*Blo)[KP],
    float acc[2][4][4], int wm, int wn, int g, int t4) {
    uint32_t ah[2][4], al[2][4];
    #pragma unroll
    for (int mi = 0; mi < 2; mi++) {
        int r0 = wm * 32 + mi * 16 + g;
        const uint32_t* ph0 = (const uint32_t*)Ahi[r0];
        const uint32_t* ph1 = (const uint32_t*)Ahi[r0 + 8];
        const uint32_t* pl0 = (const uint32_t*)Alo[r0];
        const uint32_t* pl1 = (const uint32_t*)Alo[r0 + 8];
        ah[mi][0] = ph0[t4]; ah[mi][1] = ph1[t4];
        ah[mi][2] = ph0[t4 + 4]; ah[mi][3] = ph1[t4 + 4];
        al[mi][0] = pl0[t4]; al[mi][1] = pl1[t4];
        al[mi][2] = pl0[t4 + 4]; al[mi][3] = pl1[t4 + 4];
    }
    #pragma unroll
    for (int ni = 0; ni < 4; ni++) {
        int c0 = wn * 32 + ni * 8 + g;
        const uint32_t* qh = (const uint32_t*)Bhi[c0];
        const uint32_t* ql = (const uint32_t*)Blo[c0];
        uint32_t bh[2] = { qh[t4], qh[t4 + 4] };
        uint32_t bl[2] = { ql[t4], ql[t4 + 4] };
        #pragma unroll
        for (int mi = 0; mi < 2; mi++) {
            mma16(acc[mi][ni], ah[mi], bh);
            mma16(acc[mi][ni], al[mi], bh);
            mma16(acc[mi][ni], ah[mi], bl);
        }
    }
}

// ---------------- GEMM1: Bu[L,1024] = U[L,256] @ bcat^T ----------------------
__global__ __launch_bounds__(256) void k_gemm1() {
    __shared__ __align__(16) __nv_bfloat16 Ahi[2][128][KP], Alo[2][128][KP];
    __shared__ __align__(16) __nv_bfloat16 Bhi[2][64][KP],  Blo[2][64][KP];
    int t = threadIdx.x;
    int w = t >> 5, lane = t & 31, g = lane >> 2, t4 = lane & 3;
    int wm = w >> 1, wn = w & 1;
    int row0 = blockIdx.y * 128;
    int col0 = blockIdx.x * 64;

    float acc[2][4][4] = {};
    const int KT = HH / 16;  // 16

    ld_stage(Ahi[0], Alo[0], Bhi[0], Blo[0],
             g_uhi + (size_t)row0 * HH, g_ulo + (size_t)row0 * HH, HH,
             g_bchi + (size_t)col0 * HH, g_bclo + (size_t)col0 * HH, HH, t);
    CPA_COMMIT;

    for (int it = 0; it < KT; it++) {
        if (it + 1 < KT) {
            int k0 = (it + 1) * 16, b = (it + 1) & 1;
            ld_stage(Ahi[b], Alo[b], Bhi[b], Blo[b],
                     g_uhi + (size_t)row0 * HH + k0, g_ulo + (size_t)row0 * HH + k0, HH,
                     g_bchi + (size_t)col0 * HH + k0, g_bclo + (size_t)col0 * HH + k0, HH, t);
            CPA_COMMIT;
            asm volatile("cp.async.wait_group 1;");
        } else {
            asm volatile("cp.async.wait_group 0;");
        }
        __syncthreads();
        mma_stage(Ahi[it & 1], Alo[it & 1], Bhi[it & 1], Blo[it & 1], acc, wm, wn, g, t4);
        __syncthreads();
    }

    float* out = (col0 >= NS) ? g_im : g_re;
    int nbase0 = (col0 & (NS - 1)) + wn * 32;
    #pragma unroll
    for (int mi = 0; mi < 2; mi++) {
        int l0 = row0 + wm * 32 + mi * 16 + g;
        #pragma unroll
        for (int ni = 0; ni < 4; ni++) {
            int nn = nbase0 + ni * 8 + 2 * t4;
            *(float2*)&out[(size_t)l0 * NS + nn] =
                make_float2(acc[mi][ni][0], acc[mi][ni][1]);
            *(float2*)&out[(size_t)(l0 + 8) * NS + nn] =
                make_float2(acc[mi][ni][2], acc[mi][ni][3]);
        }
    }
}

// ---------------- chunk reduce ----------------------------------------------
__global__ __launch_bounds__(512) void k_chunk() {
    int c = blockIdx.x;
    int n = threadIdx.x;
    float2 lam = g_lam[n];
    float2 b = make_float2(0.f, 0.f);
    size_t base = (size_t)c * CT * NS + n;
    #pragma unroll 4
    for (int j = 0; j < CT; j++) {
        size_t idx = base + (size_t)j * NS;
        float vr = g_re[idx], vi = g_im[idx];
        float2 tt = cmul(lam, b);
        b = make_float2(tt.x + vr, tt.y + vi);
    }
    g_chunk[c * NS + n] = b;
}

// ---------------- cross-chunk scan ------------------------------------------
__global__ __launch_bounds__(512) void k_scan() {
    int n = threadIdx.x;
    float2 lamT = g_lamT[n];
    float2 p = make_float2(0.f, 0.f);
    for (int c = 0; c < NC; c++) {
        g_pref[c * NS + n] = p;
        float2 b = g_chunk[c * NS + n];
        float2 tt = cmul(lamT, p);
        p = make_float2(tt.x + b.x, tt.y + b.y);
    }
}

// ---------------- apply: states -> bf16 hi/lo [L][1024] ----------------------
__global__ __launch_bounds__(512) void k_apply() {
    int c = blockIdx.x;
    int n = threadIdx.x;
    float2 lam = g_lam[n];
    float2 carry = g_pref[c * NS + n];
    size_t base = (size_t)c * CT * NS + n;
    #pragma unroll 2
    for (int j = 0; j < CT; j++) {
        size_t idx = base + (size_t)j * NS;
        float vr = g_re[idx], vi = g_im[idx];
        float2 tt = cmul(lam, carry);
        carry = make_float2(tt.x + vr, tt.y + vi);
        size_t l = (size_t)c * CT + j;
        __nv_bfloat16 hr, lr, hi_, li_;
        bf16_split(carry.x, hr, lr);
        bf16_split(carry.y, hi_, li_);
        g_shi[l * (2 * NS) + n] = hr;       g_slo[l * (2 * NS) + n] = lr;
        g_shi[l * (2 * NS) + NS + n] = hi_; g_slo[l * (2 * NS) + NS + n] = li_;
    }
}

// ---------------- GEMM2: Y[L,256] = S[L,1024] @ cc^T + D*U -------------------
__global__ __launch_bounds__(256) void k_gemm2(const float* __restrict__ U,
                                               const float* __restrict__ Dg,
                                               float* __restrict__ Y) {
    __shared__ __align__(16) __nv_bfloat16 Ahi[2][128][KP], Alo[2][128][KP];
    __shared__ __align__(16) __nv_bfloat16 Bhi[2][64][KP],  Blo[2][64][KP];
    int t = threadIdx.x;
    int w = t >> 5, lane = t & 31, g = lane >> 2, t4 = lane & 3;
    int wm = w >> 1, wn = w & 1;
    int row0 = blockIdx.y * 128;
    int col0 = blockIdx.x * 64;

    float acc[2][4][4] = {};
    const int KT = (2 * NS) / 16;  // 64
    const int LDA = 2 * NS;

    ld_stage(Ahi[0], Alo[0], Bhi[0], Blo[0],
             g_shi + (size_t)row0 * LDA, g_slo + (size_t)row0 * LDA, LDA,
             g_cchi + (size_t)col0 * LDA, g_cclo + (size_t)col0 * LDA, LDA, t);
    CPA_COMMIT;

    for (int it = 0; it < KT; it++) {
        if (it + 1 < KT) {
            int k0 = (it + 1) * 16, b = (it + 1) & 1;
            ld_stage(Ahi[b], Alo[b], Bhi[b], Blo[b],
                     g_shi + (size_t)row0 * LDA + k0, g_slo + (size_t)row0 * LDA + k0, LDA,
                     g_cchi + (size_t)col0 * LDA + k0, g_cclo + (size_t)col0 * LDA + k0, LDA, t);
            CPA_COMMIT;
            asm volatile("cp.async.wait_group 1;");
        } else {
            asm volatile("cp.async.wait_group 0;");
        }
        __syncthreads();
        mma_stage(Ahi[it & 1], Alo[it & 1], Bhi[it & 1], Blo[it & 1], acc, wm, wn, g, t4);
        __syncthreads();
    }

    #pragma unroll
    for (int mi = 0; mi < 2; mi++) {
        int l0 = row0 + wm * 32 + mi * 16 + g;
        #pragma unroll
        for (int ni = 0; ni < 4; ni++) {
            int h = col0 + wn * 32 + ni * 8 + 2 * t4;
            float2 d2 = *(const float2*)&Dg[h];
            float2 u0 = *(const float2*)&U[(size_t)l0 * HH + h];
            float2 u1 = *(const float2*)&U[(size_t)(l0 + 8) * HH + h];
            *(float2*)&Y[(size_t)l0 * HH + h] =
                make_float2(acc[mi][ni][0] + d2.x * u0.x, acc[mi][ni][1] + d2.y * u0.y);
            *(float2*)&Y[(size_t)(l0 + 8) * HH + h] =
                make_float2(acc[mi][ni][2] + d2.x * u1.x, acc[mi][ni][3] + d2.y * u1.y);
        }
    }
}

// ---------------- launch ----------------------------------------------------
extern "C" void kernel_launch(void* const* d_in, const int* in_sizes, int n_in,
                              void* d_out, int out_size) {
    const float* U        = (const float*)d_in[0];
    const float* nu_log   = (const float*)d_in[1];
    const float* theta_lg = (const float*)d_in[2];
    const float* Bre      = (const float*)d_in[3];
    const float* Bim      = (const float*)d_in[4];
    const float* Cre      = (const float*)d_in[5];
    const float* Cim      = (const float*)d_in[6];
    const float* D        = (const float*)d_in[7];
    float* Y = (float*)d_out;

    k_setup<<<1, 512>>>(nu_log, theta_lg);
    k_splitU<<<(LL * HH / 4 + 255) / 256, 256>>>(U);
    k_bn<<<(NS * HH + 255) / 256, 256>>>(Bre, Bim);
    k_cc<<<(HH * NS + 255) / 256, 256>>>(Cre, Cim);
    k_gemm1<<<dim3(16, 256), 256>>>();
    k_chunk<<<NC, 512>>>();
    k_scan<<<1, 512>>>();
    k_apply<<<NC, 512>>>();
    k_gemm2<<<dim3(4, 256), 256>>>(U, D, Y);
}

// round 5
// speedup vs baseline: 2.3436x; 1.2233x over previous
#include <cuda_runtime.h>
#include <cuda_fp16.h>
#include <cstdint>

#define LL 32768
#define HH 256
#define NS 512
#define CT 128
#define NC 256
#define KP 24   // smem row stride in halfs (16 data + 8 pad) -> conflict-free

// ---------------- device scratch ---------------------------------------------
__device__ float  g_re[(size_t)LL * NS];          // Bu real (gemm1 out, apply in)
__device__ float  g_im[(size_t)LL * NS];          // Bu imag
__device__ __half g_sh[(size_t)LL * 2 * NS];      // states fp16 [L][1024] (re|im)
__device__ __half g_uh[(size_t)LL * HH];          // U fp16
__device__ __half g_bchi[2 * NS * HH];            // reordered gamma-B hi (fp16)
__device__ __half g_bclo[2 * NS * HH];            // reordered gamma-B lo
__device__ __half g_cchi[HH * 2 * NS];            // [256][1024]: Cre | -Cim hi
__device__ __half g_cclo[HH * 2 * NS];
__device__ float2 g_chunk[NC * NS];
__device__ float2 g_pref[NC * NS];
__device__ float2 g_lam[NS];
__device__ float2 g_lamT[NS];
__device__ float  g_gamma[NS];

// ---------------- helpers ----------------------------------------------------
__device__ __forceinline__ float2 cmul(float2 a, float2 b) {
    return make_float2(a.x * b.x - a.y * b.y, a.x * b.y + a.y * b.x);
}
__device__ __forceinline__ void h16_split(float x, __half& hi, __half& lo) {
    hi = __float2half_rn(x);
    lo = __float2half_rn(x - __half2float(hi));
}
__device__ __forceinline__ uint32_t smem_u32(const void* p) {
    return (uint32_t)__cvta_generic_to_shared(p);
}
__device__ __forceinline__ void cpa16(const void* dst_smem, const void* src) {
    asm volatile("cp.async.cg.shared.global [%0], [%1], 16;"
                 :: "r"(smem_u32(dst_smem)), "l"(src));
}
#define CPA_COMMIT asm volatile("cp.async.commit_group;")

__device__ __forceinline__ void mma16(float* c, const uint32_t* a, const uint32_t* b) {
    asm volatile(
        "mma.sync.aligned.m16n8k16.row.col.f32.f16.f16.f32 "
        "{%0,%1,%2,%3},{%4,%5,%6,%7},{%8,%9},{%0,%1,%2,%3};"
        : "+f"(c[0]), "+f"(c[1]), "+f"(c[2]), "+f"(c[3])
        : "r"(a[0]), "r"(a[1]), "r"(a[2]), "r"(a[3]), "r"(b[0]), "r"(b[1]));
}

// ---------------- setup kernels ----------------------------------------------
__global__ void k_setup(const float* __restrict__ nu_log,
                        const float* __restrict__ theta_log) {
    int n = threadIdx.x;
    if (n >= NS) return;
    float nu    = expf(nu_log[n]);
    float theta = expf(theta_log[n]);
    float mag   = expf(-nu);
    float2 lam  = make_float2(mag * cosf(theta), mag * sinf(theta));
    g_lam[n]   = lam;
    g_gamma[n] = sqrtf(fmaxf(1.0f - mag * mag, 0.0f));
    float2 t = lam;
    #pragma unroll
    for (int i = 0; i < 7; i++) t = cmul(t, t);
    g_lamT[n] = t;
}

__global__ void k_cvtU(const float* __restrict__ U) {
    size_t i = ((size_t)blockIdx.x * 256 + threadIdx.x) * 4;
    if (i >= (size_t)LL * HH) return;
    float4 v = *(const float4*)&U[i];
    __half2 a = __halves2half2(__float2half_rn(v.x), __float2half_rn(v.y));
    __half2 b = __halves2half2(__float2half_rn(v.z), __float2half_rn(v.w));
    *(__half2*)&g_uh[i]     = a;
    *(__half2*)&g_uh[i + 2] = b;
}

// bcat layout: group g = n/32 owns rows [64g, 64g+64): first 32 = re(n=32g..),
// next 32 = im. So one gemm1 N-tile (64 rows) = re+im of the same 32 states.
__global__ void k_bn(const float* __restrict__ Bre, const float* __restrict__ Bim) {
    int i = blockIdx.x * 256 + threadIdx.x;
    if (i >= NS * HH) return;
    int n = i / HH, h = i % HH;
    float gam = g_gamma[n];
    int grp = n >> 5, j = n & 31;
    size_t rr = (size_t)(grp * 64 + j) * HH + h;
    size_t ri = (size_t)(grp * 64 + 32 + j) * HH + h;
    __half hi, lo;
    h16_split(Bre[i] * gam, hi, lo);  g_bchi[rr] = hi;  g_bclo[rr] = lo;
    h16_split(Bim[i] * gam, hi, lo);  g_bchi[ri] = hi;  g_bclo[ri] = lo;
}

__global__ void k_cc(const float* __restrict__ Cre, const float* __restrict__ Cim) {
    int i = blockIdx.x * 256 + threadIdx.x;
    if (i >= HH * NS) return;
    int h = i / NS, n = i % NS;
    __half hi, lo;
    h16_split(Cre[i], hi, lo);
    g_cchi[(size_t)h * (2*NS) + n] = hi;  g_cclo[(size_t)h * (2*NS) + n] = lo;
    h16_split(-Cim[i], hi, lo);
    g_cchi[(size_t)h * (2*NS) + NS + n] = hi;  g_cclo[(size_t)h * (2*NS) + NS + n] = lo;
}

// ---------------- GEMM machinery ---------------------------------------------
// Block tile 128(M) x 64(N) x 16(K) fp16, 256 threads = 8 warps (4M x 2N),
// warp tile 32x32 = 2x4 m16n8k16, 2 passes: A*Bhi + A*Blo.

struct StageBufs {
    __half A[2][128][KP];
    __half Bh[2][64][KP];
    __half Bl[2][64][KP];
};

__device__ __forceinline__ void ld_stage(__half (*A)[KP], __half (*Bh)[KP], __half (*Bl)[KP],
                                         const __half* gA, int lda,
                                         const __half* gBh, const __half* gBl, int ldb, int t) {
    {
        int r = t >> 1, kc = t & 1;            // 128 rows x 2 x 16B
        cpa16(&A[r][kc * 8], gA + (size_t)r * lda + kc * 8);
    }
    if (t < 128) {
        int r = t >> 1, kc = t & 1;            // 64 rows x 2
        cpa16(&Bh[r][kc * 8], gBh + (size_t)r * ldb + kc * 8);
    } else {
        int t2 = t - 128;
        int r = t2 >> 1, kc = t2 & 1;
        cpa16(&Bl[r][kc * 8], gBl + (size_t)r * ldb + kc * 8);
    }
}

__device__ __forceinline__ void mma_stage(const __half (*A)[KP],
                                          const __half (*Bh)[KP], const __half (*Bl)[KP],
                                          float acc[2][4][4], int wm, int wn, int g, int t4) {
    uint32_t a[2][4];
    #pragma unroll
    for (int mi = 0; mi < 2; mi++) {
        int r0 = wm * 32 + mi * 16 + g;
        const uint32_t* p0 = (const uint32_t*)A[r0];
        const uint32_t* p1 = (const uint32_t*)A[r0 + 8];
        a[mi][0] = p0[t4]; a[mi][1] = p1[t4];
        a[mi][2] = p0[t4 + 4]; a[mi][3] = p1[t4 + 4];
    }
    #pragma unroll
    for (int ni = 0; ni < 4; ni++) {
        int c0 = wn * 32 + ni * 8 + g;
        const uint32_t* qh = (const uint32_t*)Bh[c0];
        const uint32_t* ql = (const uint32_t*)Bl[c0];
        uint32_t bh[2] = { qh[t4], qh[t4 + 4] };
        uint32_t bl[2] = { ql[t4], ql[t4 + 4] };
        #pragma unroll
        for (int mi = 0; mi < 2; mi++) {
            mma16(acc[mi][ni], a[mi], bh);
            mma16(acc[mi][ni], a[mi], bl);
        }
    }
}

// ---------------- GEMM1 + fused chunk reduce ---------------------------------
// grid (16, 256): x = state-group (32 n's, 64 bcat rows), y = chunk (128 rows).
union SmemG1 {
    StageBufs s;
    float ep[128][68];
};

__global__ __launch_bounds__(256) void k_gemm1() {
    __shared__ SmemG1 sm;
    int t = threadIdx.x;
    int w = t >> 5, lane = t & 31, g = lane >> 2, t4 = lane & 3;
    int wm = w >> 1, wn = w & 1;
    int row0 = blockIdx.y * 128;
    int brow0 = blockIdx.x * 64;
    int n0 = blockIdx.x * 32;

    float acc[2][4][4] = {};
    const int KT = HH / 16;  // 16

    const __half* gA  = g_uh   + (size_t)row0 * HH;
    const __half* gBh = g_bchi + (size_t)brow0 * HH;
    const __half* gBl = g_bclo + (size_t)brow0 * HH;

    ld_stage(sm.s.A[0], sm.s.Bh[0], sm.s.Bl[0], gA, HH, gBh, gBl, HH, t);
    CPA_COMMIT;

    for (int it = 0; it < KT; it++) {
        if (it + 1 < KT) {
            int k0 = (it + 1) * 16, b = (it + 1) & 1;
            ld_stage(sm.s.A[b], sm.s.Bh[b], sm.s.Bl[b],
                     gA + k0, HH, gBh + k0, gBl + k0, HH, t);
            CPA_COMMIT;
            asm volatile("cp.async.wait_group 1;");
        } else {
            asm volatile("cp.async.wait_group 0;");
        }
        __syncthreads();
        mma_stage(sm.s.A[it & 1], sm.s.Bh[it & 1], sm.s.Bl[it & 1], acc, wm, wn, g, t4);
        __syncthreads();
    }

    // stage buffers dead -> epilogue tile
    #pragma unroll
    for (int mi = 0; mi < 2; mi++) {
        int r0 = wm * 32 + mi * 16 + g;
        #pragma unroll
        for (int ni = 0; ni < 4; ni++) {
            int c = wn * 32 + ni * 8 + 2 * t4;
            *(float2*)&sm.ep[r0][c]     = make_float2(acc[mi][ni][0], acc[mi][ni][1]);
            *(float2*)&sm.ep[r0 + 8][c] = make_float2(acc[mi][ni][2], acc[mi][ni][3]);
        }
    }
    __syncthreads();

    // coalesced global write of Bu (re cols 0..31, im cols 32..63)
    #pragma unroll
    for (int i = 0; i < 32; i++) {
        int fi = t + i * 256;
        int r = fi >> 6, c = fi & 63;
        float v = sm.ep[r][c];
        if (c < 32) g_re[(size_t)(row0 + r) * NS + n0 + c] = v;
        else        g_im[(size_t)(row0 + r) * NS + n0 + (c - 32)] = v;
    }

    // fused chunk Horner: warp 0, thread j owns state n0+j
    if (t < 32) {
        float2 lam = g_lam[n0 + t];
        float2 b = make_float2(0.f, 0.f);
        #pragma unroll 4
        for (int r = 0; r < 128; r++) {
            float2 tt = cmul(lam, b);
            b = make_float2(tt.x + sm.ep[r][t], tt.y + sm.ep[r][32 + t]);
        }
        g_chunk[blockIdx.y * NS + n0 + t] = b;
    }
}

// ---------------- cross-chunk scan -------------------------------------------
__global__ __launch_bounds__(512) void k_scan() {
    int n = threadIdx.x;
    float2 lamT = g_lamT[n];
    float2 p = make_float2(0.f, 0.f);
    for (int c = 0; c < NC; c++) {
        g_pref[c * NS + n] = p;
        float2 b = g_chunk[c * NS + n];
        float2 tt = cmul(lamT, p);
        p = make_float2(tt.x + b.x, tt.y + b.y);
    }
}

// ---------------- apply: states -> fp16 [L][1024] ----------------------------
__global__ __launch_bounds__(512) void k_apply() {
    int c = blockIdx.x;
    int n = threadIdx.x;
    float2 lam = g_lam[n];
    float2 carry = g_pref[c * NS + n];
    size_t base = (size_t)c * CT * NS + n;
    #pragma unroll 2
    for (int j = 0; j < CT; j++) {
        size_t idx = base + (size_t)j * NS;
        float vr = g_re[idx], vi = g_im[idx];
        float2 tt = cmul(lam, carry);
        carry = make_float2(tt.x + vr, tt.y + vi);
        size_t l = (size_t)c * CT + j;
        g_sh[l * (2*NS) + n]      = __float2half_rn(carry.x);
        g_sh[l * (2*NS) + NS + n] = __float2half_rn(carry.y);
    }
}

// ---------------- GEMM2: Y = S @ cc^T + D*U ----------------------------------
__global__ __launch_bounds__(256) void k_gemm2(const float* __restrict__ U,
                                               const float* __restrict__ Dg,
                                               float* __restrict__ Y) {
    __shared__ StageBufs sb;
    int t = threadIdx.x;
    int w = t >> 5, lane = t & 31, g = lane >> 2, t4 = lane & 3;
    int wm = w >> 1, wn = w & 1;
    int row0 = blockIdx.y * 128;
    int col0 = blockIdx.x * 64;

    float acc[2][4][4] = {};
    const int KT = (2 * NS) / 16;  // 64
    const int LDA = 2 * NS;

    const __half* gA  = g_sh   + (size_t)row0 * LDA;
    const __half* gBh = g_cchi + (size_t)col0 * LDA;
    const __half* gBl = g_cclo + (size_t)col0 * LDA;

    ld_stage(sb.A[0], sb.Bh[0], sb.Bl[0], gA, LDA, gBh, gBl, LDA, t);
    CPA_COMMIT;

    for (int it = 0; it < KT; it++) {
        if (it + 1 < KT) {
            int k0 = (it + 1) * 16, b = (it + 1) & 1;
            ld_stage(sb.A[b], sb.Bh[b], sb.Bl[b],
                     gA + k0, LDA, gBh + k0, gBl + k0, LDA, t);
            CPA_COMMIT;
            asm volatile("cp.async.wait_group 1;");
        } else {
            asm volatile("cp.async.wait_group 0;");
        }
        __syncthreads();
        mma_stage(sb.A[it & 1], sb.Bh[it & 1], sb.Bl[it & 1], acc, wm, wn, g, t4);
        __syncthreads();
    }

    #pragma unroll
    for (int mi = 0; mi < 2; mi++) {
        int l0 = row0 + wm * 32 + mi * 16 + g;
        #pragma unroll
        for (int ni = 0; ni < 4; ni++) {
            int h = col0 + wn * 32 + ni * 8 + 2 * t4;
            float2 d2 = *(const float2*)&Dg[h];
            float2 u0 = *(const float2*)&U[(size_t)l0 * HH + h];
            float2 u1 = *(const float2*)&U[(size_t)(l0 + 8) * HH + h];
            *(float2*)&Y[(size_t)l0 * HH + h] =
                make_float2(acc[mi][ni][0] + d2.x * u0.x, acc[mi][ni][1] + d2.y * u0.y);
            *(float2*)&Y[(size_t)(l0 + 8) * HH + h] =
                make_float2(acc[mi][ni][2] + d2.x * u1.x, acc[mi][ni][3] + d2.y * u1.y);
        }
    }
}

// ---------------- launch ----------------------------------------------------
extern "C" void kernel_launch(void* const* d_in, const int* in_sizes, int n_in,
                              void* d_out, int out_size) {
    const float* U        = (const float*)d_in[0];
    const float* nu_log   = (const float*)d_in[1];
    const float* theta_lg = (const float*)d_in[2];
    const float* Bre      = (const float*)d_in[3];
    const float* Bim      = (const float*)d_in[4];
    const float* Cre      = (const float*)d_in[5];
    const float* Cim      = (const float*)d_in[6];
    const float* D        = (const float*)d_in[7];
    float* Y = (float*)d_out;

    k_setup<<<1, 512>>>(nu_log, theta_lg);
    k_cvtU<<<(LL * HH / 4 + 255) / 256, 256>>>(U);
    k_bn<<<(NS * HH + 255) / 256, 256>>>(Bre, Bim);
    k_cc<<<(HH * NS + 255) / 256, 256>>>(Cre, Cim);
    k_gemm1<<<dim3(16, 256), 256>>>();
    k_scan<<<1, 512>>>();
    k_apply<<<NC, 512>>>();
    k_gemm2<<<dim3(4, 256), 256>>>(U, D, Y);
}

// round 7
// speedup vs baseline: 2.7705x; 1.1822x over previous
#include <cuda_runtime.h>
#include <cuda_fp16.h>
#include <cstdint>

#define LL 32768
#define HH 256
#define NS 512
#define CT 128
#define NC 256

// ---------------- device scratch ---------------------------------------------
__device__ float  g_re[(size_t)LL * NS];
__device__ float  g_im[(size_t)LL * NS];
__device__ __half g_sh[(size_t)LL * 2 * NS];   // states fp16 [L][1024] (re|im)
__device__ __half g_uh[(size_t)LL * HH];       // U fp16
__device__ __half g_bchi[2 * NS * HH];         // reordered gamma-B hi
__device__ __half g_bclo[2 * NS * HH];         // reordered gamma-B lo
__device__ __half g_cchi[HH * 2 * NS];         // [256][1024]: Cre | -Cim hi
__device__ __half g_cclo[HH * 2 * NS];
__device__ float2 g_chunk[NC * NS];
__device__ float2 g_pref[NC * NS];
__device__ float2 g_lam[NS];
__device__ float2 g_lamT[NS];
__device__ float  g_gamma[NS];

// ---------------- helpers ----------------------------------------------------
__device__ __forceinline__ float2 cmul(float2 a, float2 b) {
    return make_float2(a.x * b.x - a.y * b.y, a.x * b.y + a.y * b.x);
}
__device__ __forceinline__ void h16_split(float x, __half& hi, __half& lo) {
    hi = __float2half_rn(x);
    lo = __float2half_rn(x - __half2float(hi));
}
__device__ __forceinline__ uint32_t smem_u32(const void* p) {
    return (uint32_t)__cvta_generic_to_shared(p);
}
__device__ __forceinline__ void cpa16(const void* dst_smem, const void* src) {
    asm volatile("cp.async.cg.shared.global [%0], [%1], 16;"
                 :: "r"(smem_u32(dst_smem)), "l"(src));
}
#define CPA_COMMIT asm volatile("cp.async.commit_group;")

__device__ __forceinline__ void mma16(float* c, const uint32_t* a, const uint32_t* b) {
    asm volatile(
        "mma.sync.aligned.m16n8k16.row.col.f32.f16.f16.f32 "
        "{%0,%1,%2,%3},{%4,%5,%6,%7},{%8,%9},{%0,%1,%2,%3};"
        : "+f"(c[0]), "+f"(c[1]), "+f"(c[2]), "+f"(c[3])
        : "r"(a[0]), "r"(a[1]), "r"(a[2]), "r"(a[3]), "r"(b[0]), "r"(b[1]));
}
__device__ __forceinline__ void ldm_x4(uint32_t* r, uint32_t addr) {
    asm volatile("ldmatrix.sync.aligned.m8n8.x4.shared.b16 {%0,%1,%2,%3}, [%4];"
                 : "=r"(r[0]), "=r"(r[1]), "=r"(r[2]), "=r"(r[3]) : "r"(addr));
}

// ---------------- setup kernels ----------------------------------------------
__global__ void k_setup(const float* __restrict__ nu_log,
                        const float* __restrict__ theta_log) {
    int n = threadIdx.x;
    if (n >= NS) return;
    float nu    = expf(nu_log[n]);
    float theta = expf(theta_log[n]);
    float mag   = expf(-nu);
    float2 lam  = make_float2(mag * cosf(theta), mag * sinf(theta));
    g_lam[n]   = lam;
    g_gamma[n] = sqrtf(fmaxf(1.0f - mag * mag, 0.0f));
    float2 t = lam;
    #pragma unroll
    for (int i = 0; i < 7; i++) t = cmul(t, t);
    g_lamT[n] = t;
}

__global__ void k_cvtU(const float* __restrict__ U) {
    size_t i = ((size_t)blockIdx.x * 256 + threadIdx.x) * 4;
    if (i >= (size_t)LL * HH) return;
    float4 v = *(const float4*)&U[i];
    *(__half2*)&g_uh[i]     = __halves2half2(__float2half_rn(v.x), __float2half_rn(v.y));
    *(__half2*)&g_uh[i + 2] = __halves2half2(__float2half_rn(v.z), __float2half_rn(v.w));
}

// bcat layout: group g = n/32 owns rows [64g, 64g+64): first 32 = re, next 32 = im
__global__ void k_bn(const float* __restrict__ Bre, const float* __restrict__ Bim) {
    int i = blockIdx.x * 256 + threadIdx.x;
    if (i >= NS * HH) return;
    int n = i / HH, h = i % HH;
    float gam = g_gamma[n];
    int grp = n >> 5, j = n & 31;
    size_t rr = (size_t)(grp * 64 + j) * HH + h;
    size_t ri = (size_t)(grp * 64 + 32 + j) * HH + h;
    __half hi, lo;
    h16_split(Bre[i] * gam, hi, lo);  g_bchi[rr] = hi;  g_bclo[rr] = lo;
    h16_split(Bim[i] * gam, hi, lo);  g_bchi[ri] = hi;  g_bclo[ri] = lo;
}

__global__ void k_cc(const float* __restrict__ Cre, const float* __restrict__ Cim) {
    int i = blockIdx.x * 256 + threadIdx.x;
    if (i >= HH * NS) return;
    int h = i / NS, n = i % NS;
    __half hi, lo;
    h16_split(Cre[i], hi, lo);
    g_cchi[(size_t)h * (2*NS) + n] = hi;  g_cclo[(size_t)h * (2*NS) + n] = lo;
    h16_split(-Cim[i], hi, lo);
    g_cchi[(size_t)h * (2*NS) + NS + n] = hi;  g_cclo[(size_t)h * (2*NS) + NS + n] = lo;
}

// ---------------- GEMM machinery ---------------------------------------------
// Block 128(M) x 64(N) x 32(K); 256 thr = 8 warps (4M x 2N); warp 32x32.
// B kept as hi+lo (2-pass). Smem rows 40 halfs (80B). 2-stage double buffer.
static constexpr int ROWB    = 80;            // bytes per smem row
static constexpr int A_BYTES = 128 * ROWB;    // 10240
static constexpr int B_BYTES = 64 * ROWB;     // 5120
static constexpr int STG_B   = A_BYTES + 2 * B_BYTES;  // 20480

union SmemU {
    char stg[2][STG_B];                       // 40960
    float ep[128][68];                        // 34816
};

__device__ __forceinline__ void load_stage(char* stg, const __half* gA, int lda,
                                           const __half* gBh, const __half* gBl,
                                           int ldb, int k0, int t) {
    __half* A  = (__half*)stg;
    __half* Bh = (__half*)(stg + A_BYTES);
    __half* Bl = (__half*)(stg + A_BYTES + B_BYTES);
    #pragma unroll
    for (int i = 0; i < 2; i++) {
        int idx = t + i * 256;
        int r = idx >> 2, c = idx & 3;
        cpa16(&A[r * 40 + c * 8], gA + (size_t)r * lda + k0 + c * 8);
    }
    {
        int r = t >> 2, c = t & 3;
        cpa16(&Bh[r * 40 + c * 8], gBh + (size_t)r * ldb + k0 + c * 8);
        cpa16(&Bl[r * 40 + c * 8], gBl + (size_t)r * ldb + k0 + c * 8);
    }
}

// per-thread ldmatrix byte offsets within a stage buffer
__device__ __forceinline__ void mk_offsets(int wm, int wn, int lane,
                                           uint32_t* oA, uint32_t* oB) {
    #pragma unroll
    for (int mi = 0; mi < 2; mi++) {
        int row = wm * 32 + mi * 16 + (lane & 15);
        oA[mi] = (uint32_t)(row * ROWB + (8 * (lane >> 4)) * 2);
    }
    #pragma unroll
    for (int p = 0; p < 2; p++) {
        int row = wn * 32 + p * 16 + ((lane >> 4) << 3) + (lane & 7);
        oB[p] = (uint32_t)(A_BYTES + row * ROWB + (8 * ((lane >> 3) & 1)) * 2);
    }
}

__device__ __forceinline__ void compute_stage(uint32_t sb,
                                              const uint32_t* oA, const uint32_t* oB,
                                              float acc[2][4][4]) {
    #pragma unroll
    for (int kk = 0; kk < 2; kk++) {
        uint32_t af[2][4], bh[2][4], bl[2][4];
        ldm_x4(af[0], sb + oA[0] + kk * 32);
        ldm_x4(af[1], sb + oA[1] + kk * 32);
        ldm_x4(bh[0], sb + oB[0] + kk * 32);
        ldm_x4(bh[1], sb + oB[1] + kk * 32);
        ldm_x4(bl[0], sb + oB[0] + B_BYTES + kk * 32);
        ldm_x4(bl[1], sb + oB[1] + B_BYTES + kk * 32);
        #pragma unroll
        for (int mi = 0; mi < 2; mi++)
            #pragma unroll
            for (int p = 0; p < 2; p++) {
                mma16(acc[mi][2*p],     af[mi], &bh[p][0]);
                mma16(acc[mi][2*p + 1], af[mi], &bh[p][2]);
                mma16(acc[mi][2*p],     af[mi], &bl[p][0]);
                mma16(acc[mi][2*p + 1], af[mi], &bl[p][2]);
            }
    }
}

// ---------------- GEMM1 + fused chunk reduce ---------------------------------
// grid (16, 256): x = state-group (32 n's, 64 bcat rows), y = chunk (128 L-rows)
__global__ __launch_bounds__(256) void k_gemm1() {
    __shared__ SmemU sm;
    __shared__ float2 seg[4][32];
    int t = threadIdx.x;
    int w = t >> 5, lane = t & 31, g = lane >> 2, t4 = lane & 3;
    int wm = w >> 1, wn = w & 1;
    int row0 = blockIdx.y * 128;
    int n0 = blockIdx.x * 32;

    uint32_t oA[2], oB[2];
    mk_offsets(wm, wn, lane, oA, oB);

    const __half* gA  = g_uh   + (size_t)row0 * HH;
    const __half* gBh = g_bchi + (size_t)(blockIdx.x * 64) * HH;
    const __half* gBl = g_bclo + (size_t)(blockIdx.x * 64) * HH;

    float acc[2][4][4] = {};
    const int KT = HH / 32;   // 8

    load_stage(sm.stg[0], gA, HH, gBh, gBl, HH, 0, t);
    CPA_COMMIT;

    for (int it = 0; it < KT; it++) {
        if (it + 1 < KT) {
            load_stage(sm.stg[(it + 1) & 1], gA, HH, gBh, gBl, HH, (it + 1) * 32, t);
            CPA_COMMIT;
            asm volatile("cp.async.wait_group 1;");
        } else {
            asm volatile("cp.async.wait_group 0;");
        }
        __syncthreads();
        compute_stage(smem_u32(sm.stg[it & 1]), oA, oB, acc);
        __syncthreads();
    }

    // epilogue tile (stage bufs dead)
    #pragma unroll
    for (int mi = 0; mi < 2; mi++) {
        int r0 = wm * 32 + mi * 16 + g;
        #pragma unroll
        for (int ni = 0; ni < 4; ni++) {
            int c = wn * 32 + ni * 8 + 2 * t4;
            *(float2*)&sm.ep[r0][c]     = make_float2(acc[mi][ni][0], acc[mi][ni][1]);
            *(float2*)&sm.ep[r0 + 8][c] = make_float2(acc[mi][ni][2], acc[mi][ni][3]);
        }
    }
    __syncthreads();

    // coalesced write of Bu (cols 0..31 = re, 32..63 = im)
    #pragma unroll
    for (int i = 0; i < 32; i++) {
        int fi = t + i * 256;
        int r = fi >> 6, c = fi & 63;
        float v = sm.ep[r][c];
        if (c < 32) g_re[(size_t)(row0 + r) * NS + n0 + c] = v;
        else        g_im[(size_t)(row0 + r) * NS + n0 + (c - 32)] = v;
    }

    // fused chunk Horner, 4 warps x 32-row segments + lambda^32 combine
    if (w < 4) {
        float2 lam = g_lam[n0 + lane];
        float2 b = make_float2(0.f, 0.f);
        int rbase = w * 32;
        #pragma unroll 4
        for (int r = 0; r < 32; r++) {
            float2 tt = cmul(lam, b);
            b = make_float2(tt.x + sm.ep[rbase + r][lane],
                            tt.y + sm.ep[rbase + r][32 + lane]);
        }
        seg[w][lane] = b;
    }
    __syncthreads();
    if (w == 0) {
        float2 lam = g_lam[n0 + lane];
        float2 l32 = lam;
        #pragma unroll
        for (int i = 0; i < 5; i++) l32 = cmul(l32, l32);
        float2 b = seg[0][lane];
        #pragma unroll
        for (int s = 1; s < 4; s++) {
            float2 tt = cmul(l32, b);
            b = make_float2(tt.x + seg[s][lane].x, tt.y + seg[s][lane].y);
        }
        g_chunk[blockIdx.y * NS + n0 + lane] = b;
    }
}

// ---------------- cross-chunk scan -------------------------------------------
__global__ __launch_bounds__(512) void k_scan() {
    int n = threadIdx.x;
    float2 lamT = g_lamT[n];
    float2 p = make_float2(0.f, 0.f);
    for (int c = 0; c < NC; c++) {
        g_pref[c * NS + n] = p;
        float2 b = g_chunk[c * NS + n];
        float2 tt = cmul(lamT, p);
        p = make_float2(tt.x + b.x, tt.y + b.y);
    }
}

// ---------------- apply: states -> fp16 [L][1024] ----------------------------
__global__ __launch_bounds__(512) void k_apply() {
    int c = blockIdx.x;
    int n = threadIdx.x;
    float2 lam = g_lam[n];
    float2 carry = g_pref[c * NS + n];
    size_t base = (size_t)c * CT * NS + n;
    #pragma unroll 2
    for (int j = 0; j < CT; j++) {
        size_t idx = base + (size_t)j * NS;
        float vr = g_re[idx], vi = g_im[idx];
        float2 tt = cmul(lam, carry);
        carry = make_float2(tt.x + vr, tt.y + vi);
        size_t l = (size_t)c * CT + j;
        g_sh[l * (2*NS) + n]      = __float2half_rn(carry.x);
        g_sh[l * (2*NS) + NS + n] = __float2half_rn(carry.y);
    }
}

// ---------------- GEMM2: Y = S @ cc^T + D*U ----------------------------------
// grid (4, 256): x = h-tile(64), y = L-tile(128). K = 1024.
__global__ __launch_bounds__(256) void k_gemm2(const float* __restrict__ U,
                                               const float* __restrict__ Dg,
                                               float* __restrict__ Y) {
    __shared__ SmemU sm;
    int t = threadIdx.x;
    int w = t >> 5, lane = t & 31, g = lane >> 2, t4 = lane & 3;
    int wm = w >> 1, wn = w & 1;
    int row0 = blockIdx.y * 128;
    int col0 = blockIdx.x * 64;

    uint32_t oA[2], oB[2];
    mk_offsets(wm, wn, lane, oA, oB);

    const int LDA = 2 * NS;
    const __half* gA  = g_sh   + (size_t)row0 * LDA;
    const __half* gBh = g_cchi + (size_t)col0 * LDA;
    const __half* gBl = g_cclo + (size_t)col0 * LDA;

    float acc[2][4][4] = {};
    const int KT = (2 * NS) / 32;  // 32

    load_stage(sm.stg[0], gA, LDA, gBh, gBl, LDA, 0, t);
    CPA_COMMIT;

    for (int it = 0; it < KT; it++) {
        if (it + 1 < KT) {
            load_stage(sm.stg[(it + 1) & 1], gA, LDA, gBh, gBl, LDA, (it + 1) * 32, t);
            CPA_COMMIT;
            asm volatile("cp.async.wait_group 1;");
        } else {
            asm volatile("cp.async.wait_group 0;");
        }
        __syncthreads();
        compute_stage(smem_u32(sm.stg[it & 1]), oA, oB, acc);
        __syncthreads();
    }

    #pragma unroll
    for (int mi = 0; mi < 2; mi++) {
        int l0 = row0 + wm * 32 + mi * 16 + g;
        #pragma unroll
        for (int ni = 0; ni < 4; ni++) {
            int h = col0 + wn * 32 + ni * 8 + 2 * t4;
            float2 d2 = *(const float2*)&Dg[h];
            float2 u0 = *(const float2*)&U[(size_t)l0 * HH + h];
            float2 u1 = *(const float2*)&U[(size_t)(l0 + 8) * HH + h];
            *(float2*)&Y[(size_t)l0 * HH + h] =
                make_float2(acc[mi][ni][0] + d2.x * u0.x, acc[mi][ni][1] + d2.y * u0.y);
            *(float2*)&Y[(size_t)(l0 + 8) * HH + h] =
                make_float2(acc[mi][ni][2] + d2.x * u1.x, acc[mi][ni][3] + d2.y * u1.y);
        }
    }
}

// ---------------- launch ----------------------------------------------------
extern "C" void kernel_launch(void* const* d_in, const int* in_sizes, int n_in,
                              void* d_out, int out_size) {
    const float* U        = (const float*)d_in[0];
    const float* nu_log   = (const float*)d_in[1];
    const float* theta_lg = (const float*)d_in[2];
    const float* Bre      = (const float*)d_in[3];
    const float* Bim      = (const float*)d_in[4];
    const float* Cre      = (const float*)d_in[5];
    const float* Cim      = (const float*)d_in[6];
    const float* D        = (const float*)d_in[7];
    float* Y = (float*)d_out;

    k_setup<<<1, 512>>>(nu_log, theta_lg);
    k_cvtU<<<(LL * HH / 4 + 255) / 256, 256>>>(U);
    k_bn<<<(NS * HH + 255) / 256, 256>>>(Bre, Bim);
    k_cc<<<(HH * NS + 255) / 256, 256>>>(Cre, Cim);
    k_gemm1<<<dim3(16, 256), 256>>>();
    k_scan<<<1, 512>>>();
    k_apply<<<NC, 512>>>();
    k_gemm2<<<dim3(4, 256), 256>>>(U, D, Y);
}

// round 9
// speedup vs baseline: 2.9952x; 1.0811x over previous
#include <cuda_runtime.h>
#include <cuda_fp16.h>
#include <cstdint>

#define LL 32768
#define HH 256
#define NS 512
#define CT 128
#define NC 256

// ---------------- device scratch ---------------------------------------------
__device__ __half g_bur[(size_t)LL * NS];      // Bu real fp16
__device__ __half g_bui[(size_t)LL * NS];      // Bu imag fp16
__device__ __half g_sh[(size_t)LL * 2 * NS];   // states fp16 [L][1024] (re|im)
__device__ __half g_uh[(size_t)LL * HH];       // U fp16
__device__ __half g_bchi[2 * NS * HH];         // reordered gamma-B hi
__device__ __half g_bclo[2 * NS * HH];         // reordered gamma-B lo
__device__ __half g_cchi[HH * 2 * NS];         // [256][1024]: Cre | -Cim hi
__device__ __half g_cclo[HH * 2 * NS];
__device__ float2 g_chunk[NC * NS];
__device__ float2 g_pref[NC * NS];
__device__ float2 g_lam[NS];
__device__ float2 g_lamT[NS];
__device__ float  g_gamma[NS];

// ---------------- helpers ----------------------------------------------------
__device__ __forceinline__ float2 cmul(float2 a, float2 b) {
    return make_float2(a.x * b.x - a.y * b.y, a.x * b.y + a.y * b.x);
}
__device__ __forceinline__ void h16_split(float x, __half& hi, __half& lo) {
    hi = __float2half_rn(x);
    lo = __float2half_rn(x - __half2float(hi));
}
__device__ __forceinline__ uint32_t smem_u32(const void* p) {
    return (uint32_t)__cvta_generic_to_shared(p);
}
__device__ __forceinline__ void cpa16(const void* dst_smem, const void* src) {
    asm volatile("cp.async.cg.shared.global [%0], [%1], 16;"
                 :: "r"(smem_u32(dst_smem)), "l"(src));
}
#define CPA_COMMIT asm volatile("cp.async.commit_group;")

__device__ __forceinline__ void mma16(float* c, const uint32_t* a, const uint32_t* b) {
    asm volatile(
        "mma.sync.aligned.m16n8k16.row.col.f32.f16.f16.f32 "
        "{%0,%1,%2,%3},{%4,%5,%6,%7},{%8,%9},{%0,%1,%2,%3};"
        : "+f"(c[0]), "+f"(c[1]), "+f"(c[2]), "+f"(c[3])
        : "r"(a[0]), "r"(a[1]), "r"(a[2]), "r"(a[3]), "r"(b[0]), "r"(b[1]));
}
__device__ __forceinline__ void ldm_x4(uint32_t* r, uint32_t addr) {
    asm volatile("ldmatrix.sync.aligned.m8n8.x4.shared.b16 {%0,%1,%2,%3}, [%4];"
                 : "=r"(r[0]), "=r"(r[1]), "=r"(r[2]), "=r"(r[3]) : "r"(addr));
}

// ---------------- setup kernels ----------------------------------------------
__global__ void k_setup(const float* __restrict__ nu_log,
                        const float* __restrict__ theta_log) {
    int n = threadIdx.x;
    if (n >= NS) return;
    float nu    = expf(nu_log[n]);
    float theta = expf(theta_log[n]);
    float mag   = expf(-nu);
    float2 lam  = make_float2(mag * cosf(theta), mag * sinf(theta));
    g_lam[n]   = lam;
    g_gamma[n] = sqrtf(fmaxf(1.0f - mag * mag, 0.0f));
    float2 t = lam;
    #pragma unroll
    for (int i = 0; i < 7; i++) t = cmul(t, t);
    g_lamT[n] = t;
}

__global__ void k_cvtU(const float* __restrict__ U) {
    size_t i = ((size_t)blockIdx.x * 256 + threadIdx.x) * 4;
    if (i >= (size_t)LL * HH) return;
    float4 v = *(const float4*)&U[i];
    *(__half2*)&g_uh[i]     = __halves2half2(__float2half_rn(v.x), __float2half_rn(v.y));
    *(__half2*)&g_uh[i + 2] = __halves2half2(__float2half_rn(v.z), __float2half_rn(v.w));
}

// bcat layout: group g = n/32 owns rows [64g, 64g+64): first 32 = re, next 32 = im
__global__ void k_bn(const float* __restrict__ Bre, const float* __restrict__ Bim) {
    int i = blockIdx.x * 256 + threadIdx.x;
    if (i >= NS * HH) return;
    int n = i / HH, h = i % HH;
    float gam = g_gamma[n];
    int grp = n >> 5, j = n & 31;
    size_t rr = (size_t)(grp * 64 + j) * HH + h;
    size_t ri = (size_t)(grp * 64 + 32 + j) * HH + h;
    __half hi, lo;
    h16_split(Bre[i] * gam, hi, lo);  g_bchi[rr] = hi;  g_bclo[rr] = lo;
    h16_split(Bim[i] * gam, hi, lo);  g_bchi[ri] = hi;  g_bclo[ri] = lo;
}

__global__ void k_cc(const float* __restrict__ Cre, const float* __restrict__ Cim) {
    int i = blockIdx.x * 256 + threadIdx.x;
    if (i >= HH * NS) return;
    int h = i / NS, n = i % NS;
    __half hi, lo;
    h16_split(Cre[i], hi, lo);
    g_cchi[(size_t)h * (2*NS) + n] = hi;  g_cclo[(size_t)h * (2*NS) + n] = lo;
    h16_split(-Cim[i], hi, lo);
    g_cchi[(size_t)h * (2*NS) + NS + n] = hi;  g_cclo[(size_t)h * (2*NS) + NS + n] = lo;
}

// ---------------- GEMM machinery ---------------------------------------------
// Block 128(M) x 64(N) x 32(K); 256 thr = 8 warps (4M x 2N); warp 32x32.
// B kept as hi+lo (2-pass). Rows 40 halfs (80B). 3-stage ring, 1 sync/stage.
static constexpr int ROWB    = 80;
static constexpr int A_BYTES = 128 * ROWB;             // 10240
static constexpr int B_BYTES = 64 * ROWB;              // 5120
static constexpr int STG_B   = A_BYTES + 2 * B_BYTES;  // 20480
static constexpr int SMEM_DYN = 3 * STG_B;             // 61440

__device__ __forceinline__ void load_stage(char* stg, const __half* gA, int lda,
                                           const __half* gBh, const __half* gBl,
                                           int ldb, int k0, int t) {
    __half* A  = (__half*)stg;
    __half* Bh = (__half*)(stg + A_BYTES);
    __half* Bl = (__half*)(stg + A_BYTES + B_BYTES);
    #pragma unroll
    for (int i = 0; i < 2; i++) {
        int idx = t + i * 256;
        int r = idx >> 2, c = idx & 3;
        cpa16(&A[r * 40 + c * 8], gA + (size_t)r * lda + k0 + c * 8);
    }
    {
        int r = t >> 2, c = t & 3;
        cpa16(&Bh[r * 40 + c * 8], gBh + (size_t)r * ldb + k0 + c * 8);
        cpa16(&Bl[r * 40 + c * 8], gBl + (size_t)r * ldb + k0 + c * 8);
    }
}

__device__ __forceinline__ void mk_offsets(int wm, int wn, int lane,
                                           uint32_t* oA, uint32_t* oB) {
    #pragma unroll
    for (int mi = 0; mi < 2; mi++) {
        int row = wm * 32 + mi * 16 + (lane & 15);
        oA[mi] = (uint32_t)(row * ROWB + (8 * (lane >> 4)) * 2);
    }
    #pragma unroll
    for (int p = 0; p < 2; p++) {
        int row = wn * 32 + p * 16 + ((lane >> 4) << 3) + (lane & 7);
        oB[p] = (uint32_t)(A_BYTES + row * ROWB + (8 * ((lane >> 3) & 1)) * 2);
    }
}

__device__ __forceinline__ void compute_stage(uint32_t sb,
                                              const uint32_t* oA, const uint32_t* oB,
                                              float acc[2][4][4]) {
    #pragma unroll
    for (int kk = 0; kk < 2; kk++) {
        uint32_t af[2][4], bh[2][4], bl[2][4];
        ldm_x4(af[0], sb + oA[0] + kk * 32);
        ldm_x4(af[1], sb + oA[1] + kk * 32);
        ldm_x4(bh[0], sb + oB[0] + kk * 32);
        ldm_x4(bh[1], sb + oB[1] + kk * 32);
        ldm_x4(bl[0], sb + oB[0] + B_BYTES + kk * 32);
        ldm_x4(bl[1], sb + oB[1] + B_BYTES + kk * 32);
        #pragma unroll
        for (int mi = 0; mi < 2; mi++)
            #pragma unroll
            for (int p = 0; p < 2; p++) {
                mma16(acc[mi][2*p],     af[mi], &bh[p][0]);
                mma16(acc[mi][2*p + 1], af[mi], &bh[p][2]);
                mma16(acc[mi][2*p],     af[mi], &bl[p][0]);
                mma16(acc[mi][2*p + 1], af[mi], &bl[p][2]);
            }
    }
}

// ring loop shared by both GEMMs
#define GEMM_RING(KT, GA, LDA_, GBH, GBL)                                        \
    load_stage(dynsm, GA, LDA_, GBH, GBL, LDA_, 0, t);  CPA_COMMIT;              \
    load_stage(dynsm + STG_B, GA, LDA_, GBH, GBL, LDA_, 32, t); CPA_COMMIT;      \
    for (int it = 0; it < (KT); it++) {                                          \
        if (it + 1 < (KT)) { asm volatile("cp.async.wait_group 1;"); }           \
        else               { asm volatile("cp.async.wait_group 0;"); }           \
        __syncthreads();                                                         \
        if (it + 2 < (KT)) {                                                     \
            load_stage(dynsm + ((it + 2) % 3) * STG_B, GA, LDA_, GBH, GBL,       \
                       LDA_, (it + 2) * 32, t);                                  \
            CPA_COMMIT;                                                          \
        }                                                                        \
        compute_stage(sb0 + ((it) % 3) * STG_B, oA, oB, acc);                    \
    }

// ---------------- GEMM1 + fused chunk reduce ---------------------------------
// grid (16, 256): x = state-group (32 n's, 64 bcat rows), y = chunk (128 L-rows)
__global__ __launch_bounds__(256) void k_gemm1() {
    extern __shared__ char dynsm[];
    __shared__ float2 seg[4][32];
    int t = threadIdx.x;
    int w = t >> 5, lane = t & 31, g = lane >> 2, t4 = lane & 3;
    int wm = w >> 1, wn = w & 1;
    int row0 = blockIdx.y * 128;
    int n0 = blockIdx.x * 32;
    uint32_t sb0 = smem_u32(dynsm);

    uint32_t oA[2], oB[2];
    mk_offsets(wm, wn, lane, oA, oB);

    const __half* gA  = g_uh   + (size_t)row0 * HH;
    const __half* gBh = g_bchi + (size_t)(blockIdx.x * 64) * HH;
    const __half* gBl = g_bclo + (size_t)(blockIdx.x * 64) * HH;

    float acc[2][4][4] = {};
    GEMM_RING(HH / 32, gA, HH, gBh, gBl);
    __syncthreads();

    // epilogue tile (stage bufs dead): float [128][68]
    float (*ep)[68] = (float(*)[68])dynsm;
    #pragma unroll
    for (int mi = 0; mi < 2; mi++) {
        int r0 = wm * 32 + mi * 16 + g;
        #pragma unroll
        for (int ni = 0; ni < 4; ni++) {
            int c = wn * 32 + ni * 8 + 2 * t4;
            *(float2*)&ep[r0][c]     = make_float2(acc[mi][ni][0], acc[mi][ni][1]);
            *(float2*)&ep[r0 + 8][c] = make_float2(acc[mi][ni][2], acc[mi][ni][3]);
        }
    }
    __syncthreads();

    // coalesced fp16 write of Bu (pairs): 128 rows x 32 half2 (16 re, 16 im)
    #pragma unroll
    for (int i = 0; i < 16; i++) {
        int fi = t + i * 256;
        int r = fi >> 5, p = fi & 31;
        if (p < 16) {
            __half2 v = __halves2half2(__float2half_rn(ep[r][2*p]),
                                       __float2half_rn(ep[r][2*p + 1]));
            *(__half2*)&g_bur[(size_t)(row0 + r) * NS + n0 + 2*p] = v;
        } else {
            int q = p - 16;
            __half2 v = __halves2half2(__float2half_rn(ep[r][32 + 2*q]),
                                       __float2half_rn(ep[r][32 + 2*q + 1]));
            *(__half2*)&g_bui[(size_t)(row0 + r) * NS + n0 + 2*q] = v;
        }
    }

    // fused chunk Horner, 4 warps x 32-row segments + lambda^32 combine
    if (w < 4) {
        float2 lam = g_lam[n0 + lane];
        float2 b = make_float2(0.f, 0.f);
        int rbase = w * 32;
        #pragma unroll 4
        for (int r = 0; r < 32; r++) {
            float2 tt = cmul(lam, b);
            b = make_float2(tt.x + ep[rbase + r][lane],
                            tt.y + ep[rbase + r][32 + lane]);
        }
        seg[w][lane] = b;
    }
    __syncthreads();
    if (w == 0) {
        float2 lam = g_lam[n0 + lane];
        float2 l32 = lam;
        #pragma unroll
        for (int i = 0; i < 5; i++) l32 = cmul(l32, l32);
        float2 b = seg[0][lane];
        #pragma unroll
        for (int s = 1; s < 4; s++) {
            float2 tt = cmul(l32, b);
            b = make_float2(tt.x + seg[s][lane].x, tt.y + seg[s][lane].y);
        }
        g_chunk[blockIdx.y * NS + n0 + lane] = b;
    }
}

// ---------------- cross-chunk scan -------------------------------------------
__global__ __launch_bounds__(512) void k_scan() {
    int n = threadIdx.x;
    float2 lamT = g_lamT[n];
    float2 p = make_float2(0.f, 0.f);
    for (int c = 0; c < NC; c++) {
        g_pref[c * NS + n] = p;
        float2 b = g_chunk[c * NS + n];
        float2 tt = cmul(lamT, p);
        p = make_float2(tt.x + b.x, tt.y + b.y);
    }
}

// ---------------- apply: Bu fp16 -> states fp16 [L][1024] --------------------
__global__ __launch_bounds__(512) void k_apply() {
    int c = blockIdx.x;
    int n = threadIdx.x;
    float2 lam = g_lam[n];
    float2 carry = g_pref[c * NS + n];
    size_t base = (size_t)c * CT * NS + n;
    #pragma unroll 2
    for (int j = 0; j < CT; j++) {
        size_t idx = base + (size_t)j * NS;
        float vr = __half2float(g_bur[idx]);
        float vi = __half2float(g_bui[idx]);
        float2 tt = cmul(lam, carry);
        carry = make_float2(tt.x + vr, tt.y + vi);
        size_t l = (size_t)c * CT + j;
        g_sh[l * (2*NS) + n]      = __float2half_rn(carry.x);
        g_sh[l * (2*NS) + NS + n] = __float2half_rn(carry.y);
    }
}

// ---------------- GEMM2: Y = S @ cc^T + D*U ----------------------------------
// grid (4, 256): x = h-tile(64), y = L-tile(128). K = 1024.
__global__ __launch_bounds__(256) void k_gemm2(const float* __restrict__ U,
                                               const float* __restrict__ Dg,
                                               float* __restrict__ Y) {
    extern __shared__ char dynsm[];
    int t = threadIdx.x;
    int w = t >> 5, lane = t & 31, g = lane >> 2, t4 = lane & 3;
    int wm = w >> 1, wn = w & 1;
    int row0 = blockIdx.y * 128;
    int col0 = blockIdx.x * 64;
    uint32_t sb0 = smem_u32(dynsm);

    uint32_t oA[2], oB[2];
    mk_offsets(wm, wn, lane, oA, oB);

    const int LDA = 2 * NS;
    const __half* gA  = g_sh   + (size_t)row0 * LDA;
    const __half* gBh = g_cchi + (size_t)col0 * LDA;
    const __half* gBl = g_cclo + (size_t)col0 * LDA;

    float acc[2][4][4] = {};
    GEMM_RING((2 * NS) / 32, gA, LDA, gBh, gBl);

    #pragma unroll
    for (int mi = 0; mi < 2; mi++) {
        int l0 = row0 + wm * 32 + mi * 16 + g;
        #pragma unroll
        for (int ni = 0; ni < 4; ni++) {
            int h = col0 + wn * 32 + ni * 8 + 2 * t4;
            float2 d2 = *(const float2*)&Dg[h];
            float2 u0 = *(const float2*)&U[(size_t)l0 * HH + h];
            float2 u1 = *(const float2*)&U[(size_t)(l0 + 8) * HH + h];
            *(float2*)&Y[(size_t)l0 * HH + h] =
                make_float2(acc[mi][ni][0] + d2.x * u0.x, acc[mi][ni][1] + d2.y * u0.y);
            *(float2*)&Y[(size_t)(l0 + 8) * HH + h] =
                make_float2(acc[mi][ni][2] + d2.x * u1.x, acc[mi][ni][3] + d2.y * u1.y);
        }
    }
}

// ---------------- launch ----------------------------------------------------
extern "C" void kernel_launch(void* const* d_in, const int* in_sizes, int n_in,
                              void* d_out, int out_size) {
    const float* U        = (const float*)d_in[0];
    const float* nu_log   = (const float*)d_in[1];
    const float* theta_lg = (const float*)d_in[2];
    const float* Bre      = (const float*)d_in[3];
    const float* Bim      = (const float*)d_in[4];
    const float* Cre      = (const float*)d_in[5];
    const float* Cim      = (const float*)d_in[6];
    const float* D        = (const float*)d_in[7];
    float* Y = (float*)d_out;

    // no static guards (harness rule); these are host-side attribute sets,
    // graph-capture safe, and idempotent
    cudaFuncSetAttribute(k_gemm1, cudaFuncAttributeMaxDynamicSharedMemorySize, SMEM_DYN);
    cudaFuncSetAttribute(k_gemm2, cudaFuncAttributeMaxDynamicSharedMemorySize, SMEM_DYN);

    // order chosen so k_gemm1 sits at launch slot 4 (ncu keeps landing there)
    k_setup<<<1, 512>>>(nu_log, theta_lg);
    k_cvtU<<<(LL * HH / 4 + 255) / 256, 256>>>(U);
    k_bn<<<(NS * HH + 255) / 256, 256>>>(Bre, Bim);
    k_gemm1<<<dim3(16, 256), 256, SMEM_DYN>>>();
    k_cc<<<(HH * NS + 255) / 256, 256>>>(Cre, Cim);
    k_scan<<<1, 512>>>();
    k_apply<<<NC, 512>>>();
    k_gemm2<<<dim3(4, 256), 256, SMEM_DYN>>>(U, D, Y);
}